// round 1
// baseline (speedup 1.0000x reference)
#include <cuda_runtime.h>
#include <math.h>

// Problem constants
static constexpr int S_ = 2048;
static constexpr int B_ = 8;
static constexpr int D_ = 1024;
static constexpr float SCALE_ = 0.03125f;  // 1/sqrt(1024)

// GEMM tiling
static constexpr int BM = 128, BN = 128, BK = 16, TM = 8, TN = 8, NT = 256;

// Scratch (static device memory; zero-initialized at module load; never freed)
__device__ float g_Q[(size_t)S_ * B_ * D_];
__device__ float g_K[(size_t)S_ * B_ * D_];
__device__ float g_V[(size_t)S_ * B_ * D_];
__device__ float g_X[(size_t)S_ * B_ * D_];
__device__ float g_P[(size_t)B_ * S_ * S_];

__device__ __forceinline__ float neg_inf_f() { return __int_as_float(0xff800000); }

// ---------------------------------------------------------------------------
// C[m,n] = scale * sum_k A[m,k] * B[n,k]  (+bias[n])   (both operands K-major)
// Optional per-batch strides (bsA/bsB/bsC), causal -inf masking, tril skip.
// ---------------------------------------------------------------------------
template<bool CAUSAL, bool TRIL>
__global__ __launch_bounds__(NT)
void gemm_kmajor(const float* __restrict__ A, size_t lda, size_t bsA,
                 const float* __restrict__ Bm, size_t ldb, size_t bsB,
                 float* __restrict__ C, size_t ldc, size_t bsC,
                 int K, const float* __restrict__ bias, float scale)
{
    const int jt = blockIdx.x, it = blockIdx.y, b = blockIdx.z;
    if (TRIL && jt > it) return;
    const float* Ab = A + (size_t)b * bsA;
    const float* Bb = Bm + (size_t)b * bsB;
    float* Cb = C + (size_t)b * bsC;
    const int mBase = it * BM, nBase = jt * BN;

    __shared__ float As[BK][BM + 4];
    __shared__ float Bs[BK][BN + 4];

    const int tid = threadIdx.x;
    const int tr = tid >> 4, tc = tid & 15;

    float acc[TM][TN] = {};

    for (int k0 = 0; k0 < K; k0 += BK) {
#pragma unroll
        for (int i = 0; i < 2; i++) {
            const int f = tid + i * NT;
            const int row = f >> 2;           // 0..127
            const int c4 = (f & 3) << 2;      // 0,4,8,12
            const float4 v = *reinterpret_cast<const float4*>(
                Ab + (size_t)(mBase + row) * lda + k0 + c4);
            As[c4 + 0][row] = v.x; As[c4 + 1][row] = v.y;
            As[c4 + 2][row] = v.z; As[c4 + 3][row] = v.w;
            const float4 w = *reinterpret_cast<const float4*>(
                Bb + (size_t)(nBase + row) * ldb + k0 + c4);
            Bs[c4 + 0][row] = w.x; Bs[c4 + 1][row] = w.y;
            Bs[c4 + 2][row] = w.z; Bs[c4 + 3][row] = w.w;
        }
        __syncthreads();

#pragma unroll
        for (int k = 0; k < BK; k++) {
            float ra[TM], rb[TN];
            *reinterpret_cast<float4*>(ra)     = *reinterpret_cast<const float4*>(&As[k][tr * TM]);
            *reinterpret_cast<float4*>(ra + 4) = *reinterpret_cast<const float4*>(&As[k][tr * TM + 4]);
            *reinterpret_cast<float4*>(rb)     = *reinterpret_cast<const float4*>(&Bs[k][tc * TN]);
            *reinterpret_cast<float4*>(rb + 4) = *reinterpret_cast<const float4*>(&Bs[k][tc * TN + 4]);
#pragma unroll
            for (int i2 = 0; i2 < TM; i2++)
#pragma unroll
                for (int j2 = 0; j2 < TN; j2++)
                    acc[i2][j2] = fmaf(ra[i2], rb[j2], acc[i2][j2]);
        }
        __syncthreads();
    }

#pragma unroll
    for (int i2 = 0; i2 < TM; i2++) {
        const int gi = mBase + tr * TM + i2;
#pragma unroll
        for (int j2 = 0; j2 < TN; j2++) {
            const int gj = nBase + tc * TN + j2;
            float v = acc[i2][j2] * scale;
            if (bias) v += bias[gj];
            if (CAUSAL && gj > gi) v = neg_inf_f();
            Cb[(size_t)gi * ldc + gj] = v;
        }
    }
}

// ---------------------------------------------------------------------------
// Row softmax over P[b][i][0:jEnd), jEnd = end of the diagonal 128-tile.
// Masked entries hold -inf (exp -> 0). In-place.
// ---------------------------------------------------------------------------
__global__ __launch_bounds__(256)
void softmax_rows(float* __restrict__ P)
{
    const int i = blockIdx.x, b = blockIdx.y;
    float* p = P + ((size_t)b * S_ + i) * S_;
    const int jEnd = ((i >> 7) + 1) << 7;
    const int tid = threadIdx.x;
    __shared__ float sm[8];

    float m = neg_inf_f();
    for (int j = tid; j < jEnd; j += 256) m = fmaxf(m, p[j]);
#pragma unroll
    for (int o = 16; o > 0; o >>= 1) m = fmaxf(m, __shfl_xor_sync(0xffffffffu, m, o));
    if ((tid & 31) == 0) sm[tid >> 5] = m;
    __syncthreads();
    const float rowmax = fmaxf(fmaxf(fmaxf(sm[0], sm[1]), fmaxf(sm[2], sm[3])),
                               fmaxf(fmaxf(sm[4], sm[5]), fmaxf(sm[6], sm[7])));
    __syncthreads();

    float s = 0.0f;
    for (int j = tid; j < jEnd; j += 256) {
        const float e = expf(p[j] - rowmax);
        p[j] = e;
        s += e;
    }
#pragma unroll
    for (int o = 16; o > 0; o >>= 1) s += __shfl_xor_sync(0xffffffffu, s, o);
    if ((tid & 31) == 0) sm[tid >> 5] = s;
    __syncthreads();
    const float tot = (sm[0] + sm[1]) + (sm[2] + sm[3]) + (sm[4] + sm[5]) + (sm[6] + sm[7]);
    const float inv = 1.0f / tot;
    for (int j = tid; j < jEnd; j += 256) p[j] *= inv;
}

// ---------------------------------------------------------------------------
// X[i,b,:] = sum_j P[b][i][j] * V[j,b,:]   (B operand N-major; causal K-bound)
// ---------------------------------------------------------------------------
__global__ __launch_bounds__(NT)
void gemm_pv(const float* __restrict__ P, const float* __restrict__ V,
             float* __restrict__ X)
{
    const int nt = blockIdx.x, it = blockIdx.y, b = blockIdx.z;
    const float* Pb = P + (size_t)b * S_ * S_;
    const float* Vb = V + (size_t)b * D_;
    float* Xb = X + (size_t)b * D_;
    const int mBase = it * BM, nBase = nt * BN;
    const int kmax = mBase + BM;  // j <= i  =>  j < row-tile end
    const size_t ldv = (size_t)B_ * D_;

    __shared__ float As[BK][BM + 4];
    __shared__ float Bs[BK][BN + 4];

    const int tid = threadIdx.x;
    const int tr = tid >> 4, tc = tid & 15;

    float acc[TM][TN] = {};

    for (int k0 = 0; k0 < kmax; k0 += BK) {
#pragma unroll
        for (int i = 0; i < 2; i++) {
            const int f = tid + i * NT;
            // A (= P) tile: K-major transposed store
            const int row = f >> 2;
            const int c4 = (f & 3) << 2;
            const float4 v = *reinterpret_cast<const float4*>(
                Pb + (size_t)(mBase + row) * S_ + k0 + c4);
            As[c4 + 0][row] = v.x; As[c4 + 1][row] = v.y;
            As[c4 + 2][row] = v.z; As[c4 + 3][row] = v.w;
            // B (= V) tile: rows = k, cols = n, direct store
            const int krow = f >> 5;          // 0..15
            const int c = (f & 31) << 2;      // 0..124
            *reinterpret_cast<float4*>(&Bs[krow][c]) =
                *reinterpret_cast<const float4*>(Vb + (size_t)(k0 + krow) * ldv + nBase + c);
        }
        __syncthreads();

#pragma unroll
        for (int k = 0; k < BK; k++) {
            float ra[TM], rb[TN];
            *reinterpret_cast<float4*>(ra)     = *reinterpret_cast<const float4*>(&As[k][tr * TM]);
            *reinterpret_cast<float4*>(ra + 4) = *reinterpret_cast<const float4*>(&As[k][tr * TM + 4]);
            *reinterpret_cast<float4*>(rb)     = *reinterpret_cast<const float4*>(&Bs[k][tc * TN]);
            *reinterpret_cast<float4*>(rb + 4) = *reinterpret_cast<const float4*>(&Bs[k][tc * TN + 4]);
#pragma unroll
            for (int i2 = 0; i2 < TM; i2++)
#pragma unroll
                for (int j2 = 0; j2 < TN; j2++)
                    acc[i2][j2] = fmaf(ra[i2], rb[j2], acc[i2][j2]);
        }
        __syncthreads();
    }

#pragma unroll
    for (int i2 = 0; i2 < TM; i2++) {
        const int gi = mBase + tr * TM + i2;
#pragma unroll
        for (int j2 = 0; j2 < TN; j2++) {
            const int gj = nBase + tc * TN + j2;
            Xb[(size_t)gi * ldv + gj] = acc[i2][j2];
        }
    }
}

// ---------------------------------------------------------------------------
extern "C" void kernel_launch(void* const* d_in, const int* in_sizes, int n_in,
                              void* d_out, int out_size)
{
    const float* query = (const float*)d_in[0];
    const float* key   = (const float*)d_in[1];
    const float* value = (const float*)d_in[2];
    // d_in[3] = mask (known causal; handled analytically)
    const float* Wq = (const float*)d_in[4];
    const float* bq = (const float*)d_in[5];
    const float* Wk = (const float*)d_in[6];
    const float* bk = (const float*)d_in[7];
    const float* Wv = (const float*)d_in[8];
    const float* bv = (const float*)d_in[9];
    const float* Wo = (const float*)d_in[10];
    const float* bo = (const float*)d_in[11];
    float* out = (float*)d_out;

    float* Qp; cudaGetSymbolAddress((void**)&Qp, g_Q);
    float* Kp; cudaGetSymbolAddress((void**)&Kp, g_K);
    float* Vp; cudaGetSymbolAddress((void**)&Vp, g_V);
    float* Xp; cudaGetSymbolAddress((void**)&Xp, g_X);
    float* Pp; cudaGetSymbolAddress((void**)&Pp, g_P);

    const int M = S_ * B_;           // 16384
    const dim3 blk(NT);

    // Q/K/V projections: [M, D] = in[M, D] @ W[D, D]^T + b
    const dim3 gproj(D_ / BN, M / BM, 1);
    gemm_kmajor<false, false><<<gproj, blk>>>(query, D_, 0, Wq, D_, 0, Qp, D_, 0, D_, bq, 1.0f);
    gemm_kmajor<false, false><<<gproj, blk>>>(key,   D_, 0, Wk, D_, 0, Kp, D_, 0, D_, bk, 1.0f);
    gemm_kmajor<false, false><<<gproj, blk>>>(value, D_, 0, Wv, D_, 0, Vp, D_, 0, D_, bv, 1.0f);

    // Scores: P[b][i][j] = SCALE * <q_i, k_j>, tril tiles only, diagonal masked -inf
    const dim3 gsc(S_ / BN, S_ / BM, B_);
    gemm_kmajor<true, true><<<gsc, blk>>>(
        Qp, (size_t)B_ * D_, D_,
        Kp, (size_t)B_ * D_, D_,
        Pp, S_, (size_t)S_ * S_,
        D_, nullptr, SCALE_);

    // Row softmax (in place)
    softmax_rows<<<dim3(S_, B_), 256>>>(Pp);

    // X = P @ V (causal K bound)
    const dim3 gpv(D_ / BN, S_ / BM, B_);
    gemm_pv<<<gpv, blk>>>(Pp, Vp, Xp);

    // Output projection straight to d_out
    gemm_kmajor<false, false><<<gproj, blk>>>(Xp, D_, 0, Wo, D_, 0, out, D_, 0, D_, bo, 1.0f);
}

// round 3
// speedup vs baseline: 2.5644x; 2.5644x over previous
#include <cuda_runtime.h>
#include <cuda_bf16.h>
#include <cstdint>
#include <math.h>

// ---------------------------------------------------------------------------
// Problem constants
// ---------------------------------------------------------------------------
static constexpr int S_ = 2048, B_ = 8, D_ = 1024, M_ = S_ * B_;
static constexpr float SCALE_ = 0.03125f;  // 1/sqrt(1024)

// ---------------------------------------------------------------------------
// Static scratch. Split-bf16 layout: row-major [rows][2*K]: hi at [k], lo at [K+k].
// ---------------------------------------------------------------------------
__device__ __nv_bfloat16 g_Abf[(size_t)M_ * 2 * D_];      // converted input (reused q/k/v)
__device__ __nv_bfloat16 g_Wbf[4][(size_t)D_ * 2 * D_];   // Wq,Wk,Wv,Wo split
__device__ __nv_bfloat16 g_Qbf[(size_t)M_ * 2 * D_];
__device__ __nv_bfloat16 g_Kbf[(size_t)M_ * 2 * D_];
__device__ float         g_Vf [(size_t)M_ * D_];
__device__ __nv_bfloat16 g_Vt [(size_t)B_ * D_ * 2 * S_]; // V^T split: [b][d][hi(S)|lo(S)]
__device__ float         g_P  [(size_t)B_ * S_ * S_];
__device__ __nv_bfloat16 g_Pbf[(size_t)B_ * S_ * 2 * S_];
__device__ __nv_bfloat16 g_Xbf[(size_t)M_ * 2 * D_];

// ---------------------------------------------------------------------------
// Portable PTX helpers (compute_103-safe: ldmatrix / mma.sync / cp.async)
// ---------------------------------------------------------------------------
__device__ __forceinline__ uint32_t smem_u32(const void* p) {
    uint32_t a;
    asm("{ .reg .u64 t; cvta.to.shared.u64 t, %1; cvt.u32.u64 %0, t; }" : "=r"(a) : "l"(p));
    return a;
}

__device__ __forceinline__ void ldsm4(uint32_t* r, uint32_t a) {
    asm volatile("ldmatrix.sync.aligned.m8n8.x4.shared.b16 {%0,%1,%2,%3}, [%4];"
                 : "=r"(r[0]), "=r"(r[1]), "=r"(r[2]), "=r"(r[3]) : "r"(a));
}

__device__ __forceinline__ void mma16816(float* d, const uint32_t* a, const uint32_t* b) {
    asm volatile(
        "mma.sync.aligned.m16n8k16.row.col.f32.bf16.bf16.f32 "
        "{%0,%1,%2,%3}, {%4,%5,%6,%7}, {%8,%9}, {%0,%1,%2,%3};"
        : "+f"(d[0]), "+f"(d[1]), "+f"(d[2]), "+f"(d[3])
        : "r"(a[0]), "r"(a[1]), "r"(a[2]), "r"(a[3]), "r"(b[0]), "r"(b[1]));
}

__device__ __forceinline__ void cp16(uint32_t saddr, const void* gaddr) {
    asm volatile("cp.async.cg.shared.global [%0], [%1], 16;" :: "r"(saddr), "l"(gaddr));
}
__device__ __forceinline__ void cp_commit() {
    asm volatile("cp.async.commit_group;" ::: "memory");
}
template<int N>
__device__ __forceinline__ void cp_wait() {
    asm volatile("cp.async.wait_group %0;" :: "n"(N) : "memory");
}

__device__ __forceinline__ float neg_inf_f() { return __int_as_float(0xff800000); }

// ---------------------------------------------------------------------------
// GEMM: C[m,n] = scale * sum_{k''} A''[m,k''] * B''[n,k'']  (+bias)
// K'' = 3 split parts (hi*hi + lo*hi + hi*lo), each kEff wide, chunked by 64.
// EPI: 0 = fp32 out (+bias), 1 = split-bf16 out (+bias), 3 = scores (scale+mask)
// ---------------------------------------------------------------------------
struct GArgs {
    const __nv_bfloat16* A; const __nv_bfloat16* B;
    long lda, ldb, bsA, bsB;
    long oA0, oA1, oA2, oB0, oB1, oB2;
    int  Kpart;
    float scale;
    const float* bias;
    float* outF;
    __nv_bfloat16* outH;
    long ldo, bsO, loOff;
};

static constexpr int TILE_BYTES = 16384;              // 128 rows x 128B (64 bf16)
static constexpr int GEMM_SMEM = 1024 + 4 * TILE_BYTES;  // align slack + A0 A1 B0 B1

template<int EPI, bool CAUSALK, bool TRIL>
__global__ void __launch_bounds__(256, 2) gemm_bf16x3(GArgs g)
{
    const int nt = blockIdx.x, mt = blockIdx.y, bz = blockIdx.z;
    if (TRIL && nt > mt) return;
    const int mBase = mt * 128, nBase = nt * 128;

    extern __shared__ char smem_raw[];
    const uint32_t sbase = smem_u32(smem_raw);
    const uint32_t abase = (sbase + 1023) & ~1023u;   // 1KB align => swizzle-safe

    const int tid  = threadIdx.x;
    const int lane = tid & 31;
    const int warp = tid >> 5;
    const int wm   = warp >> 1;        // 0..3 -> m offset wm*32
    const int wn   = warp & 1;         // 0..1 -> n offset wn*64

    const __nv_bfloat16* Ab = g.A + (long)bz * g.bsA;
    const __nv_bfloat16* Bb = g.B + (long)bz * g.bsB;

    const int kEff = CAUSALK ? (mBase + 128) : g.Kpart;
    const int nPer = kEff >> 6;
    const int nch  = 3 * nPer;
    const long oA[3] = { g.oA0, g.oA1, g.oA2 };
    const long oB[3] = { g.oB0, g.oB1, g.oB2 };

    // per-thread gmem/smem chunk coordinates (4 chunks A + 4 chunks B)
    // chunk id = tid + i*256; row = id>>3 (0..127), c = id&7 (16B block)
    auto issue_chunk = [&](int c) {
        const int part = c / nPer;
        const int kc   = (c - part * nPer) << 6;
        const long aoff = oA[part] + kc;
        const long boff = oB[part] + kc;
        const int buf = c & 1;
        const uint32_t sA = abase + buf * TILE_BYTES;
        const uint32_t sB = abase + 2 * TILE_BYTES + buf * TILE_BYTES;
#pragma unroll
        for (int i = 0; i < 4; i++) {
            const int id = tid + i * 256;
            const int row = id >> 3, cc = id & 7;
            const uint32_t so = (uint32_t)(row << 7) + (uint32_t)((cc ^ (row & 7)) << 4);
            cp16(sA + so, Ab + (long)(mBase + row) * g.lda + aoff + cc * 8);
            cp16(sB + so, Bb + (long)(nBase + row) * g.ldb + boff + cc * 8);
        }
        cp_commit();
    };

    float acc[2][8][4];
#pragma unroll
    for (int i = 0; i < 2; i++)
#pragma unroll
        for (int j = 0; j < 8; j++)
#pragma unroll
            for (int d = 0; d < 4; d++) acc[i][j][d] = 0.0f;

    issue_chunk(0);

    for (int c = 0; c < nch; c++) {
        if (c + 1 < nch) { issue_chunk(c + 1); cp_wait<1>(); }
        else             { cp_wait<0>(); }
        __syncthreads();

        const int buf = c & 1;
        const uint32_t sA = abase + buf * TILE_BYTES;
        const uint32_t sB = abase + 2 * TILE_BYTES + buf * TILE_BYTES;

#pragma unroll
        for (int ks = 0; ks < 4; ks++) {
            uint32_t af[2][4];
#pragma unroll
            for (int mi = 0; mi < 2; mi++) {
                const int row = wm * 32 + mi * 16 + (lane & 7) + ((lane >> 3) & 1) * 8;
                const int cc  = ks * 2 + (lane >> 4);
                ldsm4(af[mi], sA + (row << 7) + ((cc ^ (row & 7)) << 4));
            }
            uint32_t bf[4][4];
#pragma unroll
            for (int nj = 0; nj < 4; nj++) {
                const int row = wn * 64 + nj * 16 + (lane & 7) + ((lane >> 4) & 1) * 8;
                const int cc  = ks * 2 + ((lane >> 3) & 1);
                ldsm4(bf[nj], sB + (row << 7) + ((cc ^ (row & 7)) << 4));
            }
#pragma unroll
            for (int mi = 0; mi < 2; mi++)
#pragma unroll
                for (int nj = 0; nj < 4; nj++) {
                    mma16816(acc[mi][2 * nj],     af[mi], &bf[nj][0]);
                    mma16816(acc[mi][2 * nj + 1], af[mi], &bf[nj][2]);
                }
        }
        __syncthreads();
    }

    // ------------------------- epilogue (register accumulators) --------------
    const int gq = lane >> 2, tg = lane & 3;
#pragma unroll
    for (int mi = 0; mi < 2; mi++) {
#pragma unroll
        for (int half = 0; half < 2; half++) {
            const int gm = mBase + wm * 32 + mi * 16 + gq + half * 8;
#pragma unroll
            for (int ni = 0; ni < 8; ni++) {
                const int gn = nBase + wn * 64 + ni * 8 + 2 * tg;
                const float v0 = acc[mi][ni][half * 2 + 0];
                const float v1 = acc[mi][ni][half * 2 + 1];

                if (EPI == 0) {
                    float2 v;
                    v.x = v0 + g.bias[gn + 0];
                    v.y = v1 + g.bias[gn + 1];
                    *reinterpret_cast<float2*>(
                        g.outF + (long)bz * g.bsO + (long)gm * g.ldo + gn) = v;
                } else if (EPI == 1) {
                    float w0 = v0, w1 = v1;
                    if (g.bias) { w0 += g.bias[gn + 0]; w1 += g.bias[gn + 1]; }
                    const __nv_bfloat16 h0 = __float2bfloat16(w0);
                    const __nv_bfloat16 h1 = __float2bfloat16(w1);
                    const __nv_bfloat16 l0 = __float2bfloat16(w0 - __bfloat162float(h0));
                    const __nv_bfloat16 l1 = __float2bfloat16(w1 - __bfloat162float(h1));
                    __nv_bfloat16* o = g.outH + (long)bz * g.bsO + (long)gm * g.ldo + gn;
                    *reinterpret_cast<__nv_bfloat162*>(o) = __nv_bfloat162(h0, h1);
                    *reinterpret_cast<__nv_bfloat162*>(o + g.loOff) = __nv_bfloat162(l0, l1);
                } else {  // EPI == 3 : scores
                    float2 v;
                    v.x = (gn + 0 > gm) ? neg_inf_f() : v0 * g.scale;
                    v.y = (gn + 1 > gm) ? neg_inf_f() : v1 * g.scale;
                    *reinterpret_cast<float2*>(
                        g.outF + (long)bz * g.bsO + (long)gm * g.ldo + gn) = v;
                }
            }
        }
    }
}

// ---------------------------------------------------------------------------
// fp32 -> split bf16 [m][2*1024] (K fixed at 1024)
// ---------------------------------------------------------------------------
__global__ void conv_split_k1024(const float* __restrict__ in,
                                 __nv_bfloat16* __restrict__ out, long n4)
{
    const long i = (long)blockIdx.x * 256 + threadIdx.x;
    if (i >= n4) return;
    const float4 v = reinterpret_cast<const float4*>(in)[i];
    const long idx = i * 4;
    const long m = idx >> 10;
    const int  k = (int)(idx & 1023);
    __nv_bfloat16* o = out + m * 2048 + k;
    float vv[4] = { v.x, v.y, v.z, v.w };
#pragma unroll
    for (int j = 0; j < 4; j++) {
        const __nv_bfloat16 h = __float2bfloat16(vv[j]);
        o[j]        = h;
        o[1024 + j] = __float2bfloat16(vv[j] - __bfloat162float(h));
    }
}

// ---------------------------------------------------------------------------
// V fp32 [s*B+b][d] -> Vt split [b][d][hi(S)|lo(S)]
// ---------------------------------------------------------------------------
__global__ void transpose_split_v(const float* __restrict__ Vf,
                                  __nv_bfloat16* __restrict__ Vt)
{
    __shared__ float t[32][33];
    const int d0 = blockIdx.x * 32, s0 = blockIdx.y * 32, b = blockIdx.z;
    const int tx = threadIdx.x, ty = threadIdx.y;
#pragma unroll
    for (int r = 0; r < 32; r += 8)
        t[r + ty][tx] = Vf[((size_t)(s0 + r + ty) * B_ + b) * D_ + d0 + tx];
    __syncthreads();
#pragma unroll
    for (int r = 0; r < 32; r += 8) {
        const int d = d0 + r + ty, s = s0 + tx;
        const float v = t[tx][r + ty];
        const __nv_bfloat16 h = __float2bfloat16(v);
        __nv_bfloat16* o = Vt + ((size_t)b * D_ + d) * (2 * S_) + s;
        o[0]  = h;
        o[S_] = __float2bfloat16(v - __bfloat162float(h));
    }
}

// ---------------------------------------------------------------------------
// Row softmax over P[b][i][0:jEnd) in place (masked entries = -inf)
// ---------------------------------------------------------------------------
__global__ void __launch_bounds__(256) softmax_rows(float* __restrict__ P)
{
    const int i = blockIdx.x, b = blockIdx.y;
    float* p = P + ((size_t)b * S_ + i) * S_;
    const int jEnd = ((i >> 7) + 1) << 7;
    const int tid = threadIdx.x;
    __shared__ float sm[8];

    float m = neg_inf_f();
    for (int j = tid; j < jEnd; j += 256) m = fmaxf(m, p[j]);
#pragma unroll
    for (int o = 16; o > 0; o >>= 1) m = fmaxf(m, __shfl_xor_sync(0xffffffffu, m, o));
    if ((tid & 31) == 0) sm[tid >> 5] = m;
    __syncthreads();
    const float rowmax = fmaxf(fmaxf(fmaxf(sm[0], sm[1]), fmaxf(sm[2], sm[3])),
                               fmaxf(fmaxf(sm[4], sm[5]), fmaxf(sm[6], sm[7])));
    __syncthreads();

    float s = 0.0f;
    for (int j = tid; j < jEnd; j += 256) {
        const float e = expf(p[j] - rowmax);
        p[j] = e;
        s += e;
    }
#pragma unroll
    for (int o = 16; o > 0; o >>= 1) s += __shfl_xor_sync(0xffffffffu, s, o);
    if ((tid & 31) == 0) sm[tid >> 5] = s;
    __syncthreads();
    const float inv = 1.0f / ((sm[0] + sm[1]) + (sm[2] + sm[3]) + (sm[4] + sm[5]) + (sm[6] + sm[7]));
    for (int j = tid; j < jEnd; j += 256) p[j] *= inv;
}

// ---------------------------------------------------------------------------
// P fp32 -> split bf16 [b][i][hi(S)|lo(S)] for j < jEnd
// ---------------------------------------------------------------------------
__global__ void conv_P(const float* __restrict__ P, __nv_bfloat16* __restrict__ Pb)
{
    const int i = blockIdx.x, b = blockIdx.y;
    const int jEnd = ((i >> 7) + 1) << 7;
    const float* p = P + ((size_t)b * S_ + i) * S_;
    __nv_bfloat16* o = Pb + ((size_t)b * S_ + i) * (2 * S_);
    for (int j = threadIdx.x; j < jEnd; j += 256) {
        const float v = p[j];
        const __nv_bfloat16 h = __float2bfloat16(v);
        o[j]      = h;
        o[S_ + j] = __float2bfloat16(v - __bfloat162float(h));
    }
}

// ---------------------------------------------------------------------------
extern "C" void kernel_launch(void* const* d_in, const int* in_sizes, int n_in,
                              void* d_out, int out_size)
{
    const float* query = (const float*)d_in[0];
    const float* key   = (const float*)d_in[1];
    const float* value = (const float*)d_in[2];
    const float* Wq = (const float*)d_in[4];
    const float* bq = (const float*)d_in[5];
    const float* Wk = (const float*)d_in[6];
    const float* bk = (const float*)d_in[7];
    const float* Wv = (const float*)d_in[8];
    const float* bv = (const float*)d_in[9];
    const float* Wo = (const float*)d_in[10];
    const float* bo = (const float*)d_in[11];
    float* out = (float*)d_out;

    __nv_bfloat16 *Abf, *Wbf, *Qbf, *Kbf, *Vt, *Pbf, *Xbf;
    float *Vf, *P;
    cudaGetSymbolAddress((void**)&Abf, g_Abf);
    cudaGetSymbolAddress((void**)&Wbf, g_Wbf);
    cudaGetSymbolAddress((void**)&Qbf, g_Qbf);
    cudaGetSymbolAddress((void**)&Kbf, g_Kbf);
    cudaGetSymbolAddress((void**)&Vf,  g_Vf);
    cudaGetSymbolAddress((void**)&Vt,  g_Vt);
    cudaGetSymbolAddress((void**)&P,   g_P);
    cudaGetSymbolAddress((void**)&Pbf, g_Pbf);
    cudaGetSymbolAddress((void**)&Xbf, g_Xbf);

    cudaFuncSetAttribute(gemm_bf16x3<0, false, false>,
                         cudaFuncAttributeMaxDynamicSharedMemorySize, GEMM_SMEM);
    cudaFuncSetAttribute(gemm_bf16x3<1, false, false>,
                         cudaFuncAttributeMaxDynamicSharedMemorySize, GEMM_SMEM);
    cudaFuncSetAttribute(gemm_bf16x3<1, true, false>,
                         cudaFuncAttributeMaxDynamicSharedMemorySize, GEMM_SMEM);
    cudaFuncSetAttribute(gemm_bf16x3<3, false, true>,
                         cudaFuncAttributeMaxDynamicSharedMemorySize, GEMM_SMEM);

    const long wlen = (long)D_ * 2 * D_;
    const long n4w  = (long)D_ * D_ / 4;
    const long n4i  = (long)M_ * D_ / 4;

    // Weight conversions
    conv_split_k1024<<<(unsigned)((n4w + 255) / 256), 256>>>(Wq, Wbf + 0 * wlen, n4w);
    conv_split_k1024<<<(unsigned)((n4w + 255) / 256), 256>>>(Wk, Wbf + 1 * wlen, n4w);
    conv_split_k1024<<<(unsigned)((n4w + 255) / 256), 256>>>(Wv, Wbf + 2 * wlen, n4w);
    conv_split_k1024<<<(unsigned)((n4w + 255) / 256), 256>>>(Wo, Wbf + 3 * wlen, n4w);

    GArgs a{};
    a.Kpart = D_;
    a.scale = 1.0f;

    const dim3 gproj(D_ / 128, M_ / 128, 1);

    // ---- Q projection ----
    conv_split_k1024<<<(unsigned)((n4i + 255) / 256), 256>>>(query, Abf, n4i);
    a.A = Abf; a.lda = 2 * D_; a.bsA = 0; a.oA0 = 0; a.oA1 = D_; a.oA2 = 0;
    a.B = Wbf + 0 * wlen; a.ldb = 2 * D_; a.bsB = 0; a.oB0 = 0; a.oB1 = 0; a.oB2 = D_;
    a.bias = bq; a.outH = Qbf; a.ldo = 2 * D_; a.bsO = 0; a.loOff = D_;
    gemm_bf16x3<1, false, false><<<gproj, 256, GEMM_SMEM>>>(a);

    // ---- K projection ----
    conv_split_k1024<<<(unsigned)((n4i + 255) / 256), 256>>>(key, Abf, n4i);
    a.B = Wbf + 1 * wlen; a.bias = bk; a.outH = Kbf;
    gemm_bf16x3<1, false, false><<<gproj, 256, GEMM_SMEM>>>(a);

    // ---- V projection (fp32 out) + transpose/split ----
    conv_split_k1024<<<(unsigned)((n4i + 255) / 256), 256>>>(value, Abf, n4i);
    a.B = Wbf + 2 * wlen; a.bias = bv; a.outH = nullptr;
    a.outF = Vf; a.ldo = D_; a.bsO = 0;
    gemm_bf16x3<0, false, false><<<gproj, 256, GEMM_SMEM>>>(a);
    transpose_split_v<<<dim3(D_ / 32, S_ / 32, B_), dim3(32, 8)>>>(Vf, Vt);

    // ---- Scores: P[b][i][j] = SCALE * <q_i, k_j>, tril tiles, causal mask ----
    GArgs sc{};
    sc.A = Qbf; sc.lda = (long)B_ * 2 * D_; sc.bsA = 2 * D_;
    sc.oA0 = 0; sc.oA1 = D_; sc.oA2 = 0;
    sc.B = Kbf; sc.ldb = (long)B_ * 2 * D_; sc.bsB = 2 * D_;
    sc.oB0 = 0; sc.oB1 = 0; sc.oB2 = D_;
    sc.Kpart = D_; sc.scale = SCALE_; sc.bias = nullptr;
    sc.outF = P; sc.ldo = S_; sc.bsO = (long)S_ * S_;
    gemm_bf16x3<3, false, true><<<dim3(S_ / 128, S_ / 128, B_), 256, GEMM_SMEM>>>(sc);

    // ---- softmax + P split ----
    softmax_rows<<<dim3(S_, B_), 256>>>(P);
    conv_P<<<dim3(S_, B_), 256>>>(P, Pbf);

    // ---- X = P @ V (causal K bound), split-bf16 out ----
    GArgs pv{};
    pv.A = Pbf; pv.lda = 2 * S_; pv.bsA = (long)S_ * 2 * S_;
    pv.oA0 = 0; pv.oA1 = S_; pv.oA2 = 0;
    pv.B = Vt; pv.ldb = 2 * S_; pv.bsB = (long)D_ * 2 * S_;
    pv.oB0 = 0; pv.oB1 = 0; pv.oB2 = S_;
    pv.Kpart = S_; pv.scale = 1.0f; pv.bias = nullptr;
    pv.outH = Xbf; pv.ldo = (long)B_ * 2 * D_; pv.bsO = 2 * D_; pv.loOff = D_;
    gemm_bf16x3<1, true, false><<<dim3(D_ / 128, S_ / 128, B_), 256, GEMM_SMEM>>>(pv);

    // ---- Output projection (fp32 to d_out) ----
    GArgs op{};
    op.A = Xbf; op.lda = 2 * D_; op.bsA = 0; op.oA0 = 0; op.oA1 = D_; op.oA2 = 0;
    op.B = Wbf + 3 * wlen; op.ldb = 2 * D_; op.bsB = 0; op.oB0 = 0; op.oB1 = 0; op.oB2 = D_;
    op.Kpart = D_; op.scale = 1.0f; op.bias = bo;
    op.outF = out; op.ldo = D_; op.bsO = 0;
    gemm_bf16x3<0, false, false><<<gproj, 256, GEMM_SMEM>>>(op);
}

// round 4
// speedup vs baseline: 2.6160x; 1.0201x over previous
#include <cuda_runtime.h>
#include <cuda_bf16.h>
#include <cstdint>
#include <math.h>

// ---------------------------------------------------------------------------
// Problem constants
// ---------------------------------------------------------------------------
static constexpr int S_ = 2048, B_ = 8, D_ = 1024, M_ = S_ * B_;
static constexpr float SCALE_ = 0.03125f;  // 1/sqrt(1024)

// ---------------------------------------------------------------------------
// Static scratch. Split-bf16 layout: row-major [rows][2*K]: hi at [k], lo at [K+k].
// ---------------------------------------------------------------------------
__device__ __nv_bfloat16 g_Abf[(size_t)M_ * 2 * D_];      // converted input (reused q/k/v)
__device__ __nv_bfloat16 g_Wbf[4][(size_t)D_ * 2 * D_];   // Wq,Wk,Wv,Wo split
__device__ __nv_bfloat16 g_Qbf[(size_t)M_ * 2 * D_];
__device__ __nv_bfloat16 g_Kbf[(size_t)M_ * 2 * D_];
__device__ float         g_Vf [(size_t)M_ * D_];
__device__ __nv_bfloat16 g_Vt [(size_t)B_ * D_ * 2 * S_]; // V^T split: [b][d][hi(S)|lo(S)]
__device__ float         g_P  [(size_t)B_ * S_ * S_];
__device__ __nv_bfloat16 g_Pbf[(size_t)B_ * S_ * 2 * S_];
__device__ __nv_bfloat16 g_Xbf[(size_t)M_ * 2 * D_];

// ---------------------------------------------------------------------------
// Portable PTX helpers (compute_103-safe: ldmatrix / mma.sync / cp.async)
// ---------------------------------------------------------------------------
__device__ __forceinline__ uint32_t smem_u32(const void* p) {
    uint32_t a;
    asm("{ .reg .u64 t; cvta.to.shared.u64 t, %1; cvt.u32.u64 %0, t; }" : "=r"(a) : "l"(p));
    return a;
}

__device__ __forceinline__ void ldsm4(uint32_t* r, uint32_t a) {
    asm volatile("ldmatrix.sync.aligned.m8n8.x4.shared.b16 {%0,%1,%2,%3}, [%4];"
                 : "=r"(r[0]), "=r"(r[1]), "=r"(r[2]), "=r"(r[3]) : "r"(a));
}

__device__ __forceinline__ void mma16816(float* d, const uint32_t* a, const uint32_t* b) {
    asm volatile(
        "mma.sync.aligned.m16n8k16.row.col.f32.bf16.bf16.f32 "
        "{%0,%1,%2,%3}, {%4,%5,%6,%7}, {%8,%9}, {%0,%1,%2,%3};"
        : "+f"(d[0]), "+f"(d[1]), "+f"(d[2]), "+f"(d[3])
        : "r"(a[0]), "r"(a[1]), "r"(a[2]), "r"(a[3]), "r"(b[0]), "r"(b[1]));
}

__device__ __forceinline__ void cp16(uint32_t saddr, const void* gaddr) {
    asm volatile("cp.async.cg.shared.global [%0], [%1], 16;" :: "r"(saddr), "l"(gaddr));
}
__device__ __forceinline__ void cp_commit() {
    asm volatile("cp.async.commit_group;" ::: "memory");
}
template<int N>
__device__ __forceinline__ void cp_wait() {
    asm volatile("cp.async.wait_group %0;" :: "n"(N) : "memory");
}

__device__ __forceinline__ float neg_inf_f() { return __int_as_float(0xff800000); }

__device__ __forceinline__ uint32_t pack_bf2(float a, float b) {
    __nv_bfloat162 h = __floats2bfloat162_rn(a, b);
    return *reinterpret_cast<uint32_t*>(&h);
}

// ---------------------------------------------------------------------------
// GEMM: C[m,n] = scale * sum_{k''} A''[m,k''] * B''[n,k'']  (+bias)
// K'' = 3 split parts (hi*hi + lo*hi + hi*lo), each kEff wide, chunked by 64.
// EPI: 0 = fp32 out (+bias), 1 = split-bf16 out (+bias), 3 = scores (scale+mask)
// ---------------------------------------------------------------------------
struct GArgs {
    const __nv_bfloat16* A; const __nv_bfloat16* B;
    long lda, ldb, bsA, bsB;
    long oA0, oA1, oA2, oB0, oB1, oB2;
    int  Kpart;
    float scale;
    const float* bias;
    float* outF;
    __nv_bfloat16* outH;
    long ldo, bsO, loOff;
};

static constexpr int TILE_BYTES = 16384;  // 128 rows x 128B (64 bf16)
static constexpr int STAGES = 3;
static constexpr int GEMM_SMEM = 1024 + 2 * STAGES * TILE_BYTES;  // 97.25 KB

template<int EPI, bool CAUSALK, bool TRIL>
__global__ void __launch_bounds__(256, 2) gemm_bf16x3(GArgs g)
{
    const int nt = blockIdx.x, mt = blockIdx.y, bz = blockIdx.z;
    if (TRIL && nt > mt) return;
    const int mBase = mt * 128, nBase = nt * 128;

    extern __shared__ char smem_raw[];
    const uint32_t sbase = smem_u32(smem_raw);
    const uint32_t abase = (sbase + 1023) & ~1023u;   // 1KB align => swizzle-safe

    const int tid  = threadIdx.x;
    const int lane = tid & 31;
    const int warp = tid >> 5;
    const int wm   = warp >> 1;        // 0..3 -> m offset wm*32
    const int wn   = warp & 1;         // 0..1 -> n offset wn*64

    const __nv_bfloat16* Ab = g.A + (long)bz * g.bsA;
    const __nv_bfloat16* Bb = g.B + (long)bz * g.bsB;

    const int kEff = CAUSALK ? (mBase + 128) : g.Kpart;
    const int nPer = kEff >> 6;
    const int nch  = 3 * nPer;           // >= 6 always
    const long oA[3] = { g.oA0, g.oA1, g.oA2 };
    const long oB[3] = { g.oB0, g.oB1, g.oB2 };

    auto issue_chunk = [&](int c) {
        const int part = c / nPer;
        const int kc   = (c - part * nPer) << 6;
        const long aoff = oA[part] + kc;
        const long boff = oB[part] + kc;
        const int buf = c % STAGES;
        const uint32_t sA = abase + buf * TILE_BYTES;
        const uint32_t sB = abase + STAGES * TILE_BYTES + buf * TILE_BYTES;
#pragma unroll
        for (int i = 0; i < 4; i++) {
            const int id = tid + i * 256;
            const int row = id >> 3, cc = id & 7;
            const uint32_t so = (uint32_t)(row << 7) + (uint32_t)((cc ^ (row & 7)) << 4);
            cp16(sA + so, Ab + (long)(mBase + row) * g.lda + aoff + cc * 8);
            cp16(sB + so, Bb + (long)(nBase + row) * g.ldb + boff + cc * 8);
        }
        cp_commit();
    };

    float acc[2][8][4];
#pragma unroll
    for (int i = 0; i < 2; i++)
#pragma unroll
        for (int j = 0; j < 8; j++)
#pragma unroll
            for (int d = 0; d < 4; d++) acc[i][j][d] = 0.0f;

    issue_chunk(0);
    issue_chunk(1);

    for (int c = 0; c < nch; c++) {
        if (c == nch - 1) cp_wait<0>(); else cp_wait<STAGES - 2>();
        __syncthreads();

        if (c + STAGES - 1 < nch) issue_chunk(c + STAGES - 1);

        const int buf = c % STAGES;
        const uint32_t sA = abase + buf * TILE_BYTES;
        const uint32_t sB = abase + STAGES * TILE_BYTES + buf * TILE_BYTES;

#pragma unroll
        for (int ks = 0; ks < 4; ks++) {
            uint32_t af[2][4];
#pragma unroll
            for (int mi = 0; mi < 2; mi++) {
                const int row = wm * 32 + mi * 16 + (lane & 7) + ((lane >> 3) & 1) * 8;
                const int cc  = ks * 2 + (lane >> 4);
                ldsm4(af[mi], sA + (row << 7) + ((cc ^ (row & 7)) << 4));
            }
            uint32_t bf[4][4];
#pragma unroll
            for (int nj = 0; nj < 4; nj++) {
                const int row = wn * 64 + nj * 16 + (lane & 7) + ((lane >> 4) & 1) * 8;
                const int cc  = ks * 2 + ((lane >> 3) & 1);
                ldsm4(bf[nj], sB + (row << 7) + ((cc ^ (row & 7)) << 4));
            }
#pragma unroll
            for (int mi = 0; mi < 2; mi++)
#pragma unroll
                for (int nj = 0; nj < 4; nj++) {
                    mma16816(acc[mi][2 * nj],     af[mi], &bf[nj][0]);
                    mma16816(acc[mi][2 * nj + 1], af[mi], &bf[nj][2]);
                }
        }
    }

    // ------------------------- epilogue (register accumulators) --------------
    const int gq = lane >> 2, tg = lane & 3;
#pragma unroll
    for (int mi = 0; mi < 2; mi++) {
#pragma unroll
        for (int half = 0; half < 2; half++) {
            const int gm = mBase + wm * 32 + mi * 16 + gq + half * 8;
#pragma unroll
            for (int ni = 0; ni < 8; ni++) {
                const int gn = nBase + wn * 64 + ni * 8 + 2 * tg;
                const float v0 = acc[mi][ni][half * 2 + 0];
                const float v1 = acc[mi][ni][half * 2 + 1];

                if (EPI == 0) {
                    float2 v;
                    v.x = v0 + g.bias[gn + 0];
                    v.y = v1 + g.bias[gn + 1];
                    *reinterpret_cast<float2*>(
                        g.outF + (long)bz * g.bsO + (long)gm * g.ldo + gn) = v;
                } else if (EPI == 1) {
                    float w0 = v0, w1 = v1;
                    if (g.bias) { w0 += g.bias[gn + 0]; w1 += g.bias[gn + 1]; }
                    const __nv_bfloat16 h0 = __float2bfloat16(w0);
                    const __nv_bfloat16 h1 = __float2bfloat16(w1);
                    const __nv_bfloat16 l0 = __float2bfloat16(w0 - __bfloat162float(h0));
                    const __nv_bfloat16 l1 = __float2bfloat16(w1 - __bfloat162float(h1));
                    __nv_bfloat16* o = g.outH + (long)bz * g.bsO + (long)gm * g.ldo + gn;
                    *reinterpret_cast<__nv_bfloat162*>(o) = __nv_bfloat162(h0, h1);
                    *reinterpret_cast<__nv_bfloat162*>(o + g.loOff) = __nv_bfloat162(l0, l1);
                } else {  // EPI == 3 : scores
                    float2 v;
                    v.x = (gn + 0 > gm) ? neg_inf_f() : v0 * g.scale;
                    v.y = (gn + 1 > gm) ? neg_inf_f() : v1 * g.scale;
                    *reinterpret_cast<float2*>(
                        g.outF + (long)bz * g.bsO + (long)gm * g.ldo + gn) = v;
                }
            }
        }
    }
}

// ---------------------------------------------------------------------------
// fp32 -> split bf16 [m][2*1024] (K fixed at 1024); 8B vector stores
// ---------------------------------------------------------------------------
__global__ void conv_split_k1024(const float* __restrict__ in,
                                 __nv_bfloat16* __restrict__ out, long n4)
{
    const long i = (long)blockIdx.x * 256 + threadIdx.x;
    if (i >= n4) return;
    const float4 v = reinterpret_cast<const float4*>(in)[i];
    const long idx = i * 4;
    const long m = idx >> 10;
    const int  k = (int)(idx & 1023);

    const __nv_bfloat16 h0 = __float2bfloat16(v.x);
    const __nv_bfloat16 h1 = __float2bfloat16(v.y);
    const __nv_bfloat16 h2 = __float2bfloat16(v.z);
    const __nv_bfloat16 h3 = __float2bfloat16(v.w);
    uint2 hp, lp;
    hp.x = pack_bf2(v.x, v.y);
    hp.y = pack_bf2(v.z, v.w);
    lp.x = pack_bf2(v.x - __bfloat162float(h0), v.y - __bfloat162float(h1));
    lp.y = pack_bf2(v.z - __bfloat162float(h2), v.w - __bfloat162float(h3));

    __nv_bfloat16* o = out + m * 2048 + k;
    *reinterpret_cast<uint2*>(o)        = hp;
    *reinterpret_cast<uint2*>(o + 1024) = lp;
}

// ---------------------------------------------------------------------------
// V fp32 [s*B+b][d] -> Vt split [b][d][hi(S)|lo(S)]
// ---------------------------------------------------------------------------
__global__ void transpose_split_v(const float* __restrict__ Vf,
                                  __nv_bfloat16* __restrict__ Vt)
{
    __shared__ float t[32][33];
    const int d0 = blockIdx.x * 32, s0 = blockIdx.y * 32, b = blockIdx.z;
    const int tx = threadIdx.x, ty = threadIdx.y;
#pragma unroll
    for (int r = 0; r < 32; r += 8)
        t[r + ty][tx] = Vf[((size_t)(s0 + r + ty) * B_ + b) * D_ + d0 + tx];
    __syncthreads();
#pragma unroll
    for (int r = 0; r < 32; r += 8) {
        const int d = d0 + r + ty, s = s0 + tx;
        const float v = t[tx][r + ty];
        const __nv_bfloat16 h = __float2bfloat16(v);
        __nv_bfloat16* o = Vt + ((size_t)b * D_ + d) * (2 * S_) + s;
        o[0]  = h;
        o[S_] = __float2bfloat16(v - __bfloat162float(h));
    }
}

// ---------------------------------------------------------------------------
// Fused row softmax + split-bf16 emit.
// Reads fp32 scores P[b][i][0:jEnd) (masked = -inf), writes split Pbf only.
// ---------------------------------------------------------------------------
__global__ void __launch_bounds__(256) softmax_split(const float* __restrict__ P,
                                                     __nv_bfloat16* __restrict__ Pb)
{
    const int i = blockIdx.x, b = blockIdx.y;
    const float* p = P + ((size_t)b * S_ + i) * S_;
    __nv_bfloat16* o = Pb + ((size_t)b * S_ + i) * (2 * S_);
    const int jEnd = ((i >> 7) + 1) << 7;
    const int tid = threadIdx.x;
    __shared__ float sm[8];

    float m = neg_inf_f();
    for (int j = tid * 2; j < jEnd; j += 512) {
        const float2 v = *reinterpret_cast<const float2*>(p + j);
        m = fmaxf(m, fmaxf(v.x, v.y));
    }
#pragma unroll
    for (int off = 16; off > 0; off >>= 1) m = fmaxf(m, __shfl_xor_sync(0xffffffffu, m, off));
    if ((tid & 31) == 0) sm[tid >> 5] = m;
    __syncthreads();
    const float rowmax = fmaxf(fmaxf(fmaxf(sm[0], sm[1]), fmaxf(sm[2], sm[3])),
                               fmaxf(fmaxf(sm[4], sm[5]), fmaxf(sm[6], sm[7])));
    __syncthreads();

    float s = 0.0f;
    for (int j = tid * 2; j < jEnd; j += 512) {
        const float2 v = *reinterpret_cast<const float2*>(p + j);
        s += expf(v.x - rowmax) + expf(v.y - rowmax);
    }
#pragma unroll
    for (int off = 16; off > 0; off >>= 1) s += __shfl_xor_sync(0xffffffffu, s, off);
    if ((tid & 31) == 0) sm[tid >> 5] = s;
    __syncthreads();
    const float inv = 1.0f / ((sm[0] + sm[1]) + (sm[2] + sm[3]) + (sm[4] + sm[5]) + (sm[6] + sm[7]));

    for (int j = tid * 2; j < jEnd; j += 512) {
        const float2 v = *reinterpret_cast<const float2*>(p + j);
        const float e0 = expf(v.x - rowmax) * inv;
        const float e1 = expf(v.y - rowmax) * inv;
        const __nv_bfloat16 h0 = __float2bfloat16(e0);
        const __nv_bfloat16 h1 = __float2bfloat16(e1);
        *reinterpret_cast<uint32_t*>(o + j) = pack_bf2(e0, e1);
        *reinterpret_cast<uint32_t*>(o + S_ + j) =
            pack_bf2(e0 - __bfloat162float(h0), e1 - __bfloat162float(h1));
    }
}

// ---------------------------------------------------------------------------
extern "C" void kernel_launch(void* const* d_in, const int* in_sizes, int n_in,
                              void* d_out, int out_size)
{
    const float* query = (const float*)d_in[0];
    const float* key   = (const float*)d_in[1];
    const float* value = (const float*)d_in[2];
    const float* Wq = (const float*)d_in[4];
    const float* bq = (const float*)d_in[5];
    const float* Wk = (const float*)d_in[6];
    const float* bk = (const float*)d_in[7];
    const float* Wv = (const float*)d_in[8];
    const float* bv = (const float*)d_in[9];
    const float* Wo = (const float*)d_in[10];
    const float* bo = (const float*)d_in[11];
    float* out = (float*)d_out;

    __nv_bfloat16 *Abf, *Wbf, *Qbf, *Kbf, *Vt, *Pbf, *Xbf;
    float *Vf, *P;
    cudaGetSymbolAddress((void**)&Abf, g_Abf);
    cudaGetSymbolAddress((void**)&Wbf, g_Wbf);
    cudaGetSymbolAddress((void**)&Qbf, g_Qbf);
    cudaGetSymbolAddress((void**)&Kbf, g_Kbf);
    cudaGetSymbolAddress((void**)&Vf,  g_Vf);
    cudaGetSymbolAddress((void**)&Vt,  g_Vt);
    cudaGetSymbolAddress((void**)&P,   g_P);
    cudaGetSymbolAddress((void**)&Pbf, g_Pbf);
    cudaGetSymbolAddress((void**)&Xbf, g_Xbf);

    cudaFuncSetAttribute(gemm_bf16x3<0, false, false>,
                         cudaFuncAttributeMaxDynamicSharedMemorySize, GEMM_SMEM);
    cudaFuncSetAttribute(gemm_bf16x3<1, false, false>,
                         cudaFuncAttributeMaxDynamicSharedMemorySize, GEMM_SMEM);
    cudaFuncSetAttribute(gemm_bf16x3<1, true, false>,
                         cudaFuncAttributeMaxDynamicSharedMemorySize, GEMM_SMEM);
    cudaFuncSetAttribute(gemm_bf16x3<3, false, true>,
                         cudaFuncAttributeMaxDynamicSharedMemorySize, GEMM_SMEM);

    const long wlen = (long)D_ * 2 * D_;
    const long n4w  = (long)D_ * D_ / 4;
    const long n4i  = (long)M_ * D_ / 4;

    // Weight conversions
    conv_split_k1024<<<(unsigned)((n4w + 255) / 256), 256>>>(Wq, Wbf + 0 * wlen, n4w);
    conv_split_k1024<<<(unsigned)((n4w + 255) / 256), 256>>>(Wk, Wbf + 1 * wlen, n4w);
    conv_split_k1024<<<(unsigned)((n4w + 255) / 256), 256>>>(Wv, Wbf + 2 * wlen, n4w);
    conv_split_k1024<<<(unsigned)((n4w + 255) / 256), 256>>>(Wo, Wbf + 3 * wlen, n4w);

    GArgs a{};
    a.Kpart = D_;
    a.scale = 1.0f;

    const dim3 gproj(D_ / 128, M_ / 128, 1);

    // ---- Q projection ----
    conv_split_k1024<<<(unsigned)((n4i + 255) / 256), 256>>>(query, Abf, n4i);
    a.A = Abf; a.lda = 2 * D_; a.bsA = 0; a.oA0 = 0; a.oA1 = D_; a.oA2 = 0;
    a.B = Wbf + 0 * wlen; a.ldb = 2 * D_; a.bsB = 0; a.oB0 = 0; a.oB1 = 0; a.oB2 = D_;
    a.bias = bq; a.outH = Qbf; a.ldo = 2 * D_; a.bsO = 0; a.loOff = D_;
    gemm_bf16x3<1, false, false><<<gproj, 256, GEMM_SMEM>>>(a);

    // ---- K projection ----
    conv_split_k1024<<<(unsigned)((n4i + 255) / 256), 256>>>(key, Abf, n4i);
    a.B = Wbf + 1 * wlen; a.bias = bk; a.outH = Kbf;
    gemm_bf16x3<1, false, false><<<gproj, 256, GEMM_SMEM>>>(a);

    // ---- V projection (fp32 out) + transpose/split ----
    conv_split_k1024<<<(unsigned)((n4i + 255) / 256), 256>>>(value, Abf, n4i);
    a.B = Wbf + 2 * wlen; a.bias = bv; a.outH = nullptr;
    a.outF = Vf; a.ldo = D_; a.bsO = 0;
    gemm_bf16x3<0, false, false><<<gproj, 256, GEMM_SMEM>>>(a);
    transpose_split_v<<<dim3(D_ / 32, S_ / 32, B_), dim3(32, 8)>>>(Vf, Vt);

    // ---- Scores: P[b][i][j] = SCALE * <q_i, k_j>, tril tiles, causal mask ----
    GArgs sc{};
    sc.A = Qbf; sc.lda = (long)B_ * 2 * D_; sc.bsA = 2 * D_;
    sc.oA0 = 0; sc.oA1 = D_; sc.oA2 = 0;
    sc.B = Kbf; sc.ldb = (long)B_ * 2 * D_; sc.bsB = 2 * D_;
    sc.oB0 = 0; sc.oB1 = 0; sc.oB2 = D_;
    sc.Kpart = D_; sc.scale = SCALE_; sc.bias = nullptr;
    sc.outF = P; sc.ldo = S_; sc.bsO = (long)S_ * S_;
    gemm_bf16x3<3, false, true><<<dim3(S_ / 128, S_ / 128, B_), 256, GEMM_SMEM>>>(sc);

    // ---- fused softmax + P split ----
    softmax_split<<<dim3(S_, B_), 256>>>(P, Pbf);

    // ---- X = P @ V (causal K bound), split-bf16 out ----
    GArgs pv{};
    pv.A = Pbf; pv.lda = 2 * S_; pv.bsA = (long)S_ * 2 * S_;
    pv.oA0 = 0; pv.oA1 = S_; pv.oA2 = 0;
    pv.B = Vt; pv.ldb = 2 * S_; pv.bsB = (long)D_ * 2 * S_;
    pv.oB0 = 0; pv.oB1 = 0; pv.oB2 = S_;
    pv.Kpart = S_; pv.scale = 1.0f; pv.bias = nullptr;
    pv.outH = Xbf; pv.ldo = (long)B_ * 2 * D_; pv.bsO = 2 * D_; pv.loOff = D_;
    gemm_bf16x3<1, true, false><<<dim3(D_ / 128, S_ / 128, B_), 256, GEMM_SMEM>>>(pv);

    // ---- Output projection (fp32 to d_out) ----
    GArgs op{};
    op.A = Xbf; op.lda = 2 * D_; op.bsA = 0; op.oA0 = 0; op.oA1 = D_; op.oA2 = 0;
    op.B = Wbf + 3 * wlen; op.ldb = 2 * D_; op.bsB = 0; op.oB0 = 0; op.oB1 = 0; op.oB2 = D_;
    op.Kpart = D_; op.scale = 1.0f; op.bias = bo;
    op.outF = out; op.ldo = D_; op.bsO = 0;
    gemm_bf16x3<0, false, false><<<gproj, 256, GEMM_SMEM>>>(op);
}

// round 5
// speedup vs baseline: 2.6955x; 1.0304x over previous
#include <cuda_runtime.h>
#include <cuda_bf16.h>
#include <cstdint>
#include <math.h>

// ---------------------------------------------------------------------------
// Problem constants
// ---------------------------------------------------------------------------
static constexpr int S_ = 2048, B_ = 8, D_ = 1024, M_ = S_ * B_;
static constexpr float SCALE_ = 0.03125f;  // 1/sqrt(1024)

// ---------------------------------------------------------------------------
// Static scratch. Split-bf16 layout: row-major [rows][2*K]: hi at [k], lo at [K+k].
// ---------------------------------------------------------------------------
__device__ __nv_bfloat16 g_Abf[(size_t)M_ * 2 * D_];      // converted input (reused q/k/v)
__device__ __nv_bfloat16 g_Wbf[4][(size_t)D_ * 2 * D_];   // Wq,Wk,Wv,Wo split
__device__ __nv_bfloat16 g_Qbf[(size_t)M_ * 2 * D_];
__device__ __nv_bfloat16 g_Kbf[(size_t)M_ * 2 * D_];
__device__ float         g_Vf [(size_t)M_ * D_];
__device__ __nv_bfloat16 g_Vt [(size_t)B_ * D_ * 2 * S_]; // V^T split: [b][d][hi(S)|lo(S)]
__device__ float         g_P  [(size_t)B_ * S_ * S_];
__device__ __nv_bfloat16 g_Pbf[(size_t)B_ * S_ * 2 * S_];
__device__ __nv_bfloat16 g_Xbf[(size_t)M_ * 2 * D_];

// ---------------------------------------------------------------------------
// Portable PTX helpers (compute_103-safe: ldmatrix / mma.sync / cp.async)
// ---------------------------------------------------------------------------
__device__ __forceinline__ uint32_t smem_u32(const void* p) {
    uint32_t a;
    asm("{ .reg .u64 t; cvta.to.shared.u64 t, %1; cvt.u32.u64 %0, t; }" : "=r"(a) : "l"(p));
    return a;
}

__device__ __forceinline__ void ldsm4(uint32_t* r, uint32_t a) {
    asm volatile("ldmatrix.sync.aligned.m8n8.x4.shared.b16 {%0,%1,%2,%3}, [%4];"
                 : "=r"(r[0]), "=r"(r[1]), "=r"(r[2]), "=r"(r[3]) : "r"(a));
}

__device__ __forceinline__ void mma16816(float* d, const uint32_t* a, const uint32_t* b) {
    asm volatile(
        "mma.sync.aligned.m16n8k16.row.col.f32.bf16.bf16.f32 "
        "{%0,%1,%2,%3}, {%4,%5,%6,%7}, {%8,%9}, {%0,%1,%2,%3};"
        : "+f"(d[0]), "+f"(d[1]), "+f"(d[2]), "+f"(d[3])
        : "r"(a[0]), "r"(a[1]), "r"(a[2]), "r"(a[3]), "r"(b[0]), "r"(b[1]));
}

__device__ __forceinline__ void cp16(uint32_t saddr, const void* gaddr) {
    asm volatile("cp.async.cg.shared.global [%0], [%1], 16;" :: "r"(saddr), "l"(gaddr));
}
__device__ __forceinline__ void cp_commit() {
    asm volatile("cp.async.commit_group;" ::: "memory");
}
template<int N>
__device__ __forceinline__ void cp_wait() {
    asm volatile("cp.async.wait_group %0;" :: "n"(N) : "memory");
}

__device__ __forceinline__ float neg_inf_f() { return __int_as_float(0xff800000); }

__device__ __forceinline__ uint32_t pack_bf2(float a, float b) {
    __nv_bfloat162 h = __floats2bfloat162_rn(a, b);
    return *reinterpret_cast<uint32_t*>(&h);
}

// ---------------------------------------------------------------------------
// Fused split GEMM: C[m,n] = scale * (Ahi*Bhi + Alo*Bhi + Ahi*Blo)[m,n] (+bias)
// CTA tile 256x128, warp tile 64x64 (8 warps), k-chunk 64, 2-stage cp.async.
// Per chunk: load Ahi/Alo/Blo/Bhi once, run 3 MMA passes (lh -> hh -> hl).
// EPI: 0 = fp32 out (+bias), 1 = split-bf16 out (+bias), 3 = scores (scale+mask)
// ---------------------------------------------------------------------------
struct GArgs {
    const __nv_bfloat16* A; const __nv_bfloat16* B;
    long lda, ldb, bsA, bsB;
    long oAlo, oBlo;           // element offset of the lo part within a row
    int  Kpart;
    float scale;
    const float* bias;
    float* outF;
    __nv_bfloat16* outH;
    long ldo, bsO, loOff;
};

static constexpr int A_TILE = 32768;   // 256 rows x 128B
static constexpr int B_TILE = 16384;   // 128 rows x 128B
static constexpr int STAGE  = 2 * A_TILE + 2 * B_TILE;  // 96 KB
static constexpr int GEMM_SMEM = 1024 + 2 * STAGE;      // 193 KB

template<int EPI, bool CAUSALK, bool TRIL>
__global__ void __launch_bounds__(256, 1) gemm_split(GArgs g)
{
    const int nt = blockIdx.x, mt = blockIdx.y, bz = blockIdx.z;
    if (TRIL && nt * 128 > mt * 256 + 255) return;
    const int mBase = mt * 256, nBase = nt * 128;

    extern __shared__ char smem_raw[];
    const uint32_t sbase = smem_u32(smem_raw);
    const uint32_t abase = (sbase + 1023) & ~1023u;

    const int tid  = threadIdx.x;
    const int lane = tid & 31;
    const int warp = tid >> 5;
    const int wm   = warp >> 1;        // 0..3 -> m offset wm*64
    const int wn   = warp & 1;         // 0..1 -> n offset wn*64

    const __nv_bfloat16* Ab = g.A + (long)bz * g.bsA;
    const __nv_bfloat16* Bb = g.B + (long)bz * g.bsB;

    const int kEff = CAUSALK ? (mBase + 256) : g.Kpart;
    const int nch  = kEff >> 6;

    auto issue_chunk = [&](int c) {
        const long kc = (long)(c << 6);
        const int st = c & 1;
        const uint32_t sAhi = abase + st * STAGE;
        const uint32_t sAlo = sAhi + A_TILE;
        const uint32_t sBhi = sAhi + 2 * A_TILE;
        const uint32_t sBlo = sBhi + B_TILE;
#pragma unroll
        for (int i = 0; i < 8; i++) {
            const int id = tid + i * 256;
            const int row = id >> 3, cc = id & 7;
            const uint32_t so = (uint32_t)(row << 7) + (uint32_t)((cc ^ (row & 7)) << 4);
            const __nv_bfloat16* src = Ab + (long)(mBase + row) * g.lda + kc + cc * 8;
            cp16(sAhi + so, src);
            cp16(sAlo + so, src + g.oAlo);
        }
#pragma unroll
        for (int i = 0; i < 4; i++) {
            const int id = tid + i * 256;
            const int row = id >> 3, cc = id & 7;
            const uint32_t so = (uint32_t)(row << 7) + (uint32_t)((cc ^ (row & 7)) << 4);
            const __nv_bfloat16* src = Bb + (long)(nBase + row) * g.ldb + kc + cc * 8;
            cp16(sBhi + so, src);
            cp16(sBlo + so, src + g.oBlo);
        }
        cp_commit();
    };

    float acc[4][8][4];
#pragma unroll
    for (int i = 0; i < 4; i++)
#pragma unroll
        for (int j = 0; j < 8; j++)
#pragma unroll
            for (int d = 0; d < 4; d++) acc[i][j][d] = 0.0f;

    issue_chunk(0);

    // precomputed ldsm lane addressing
    const int arow = (lane & 7) + ((lane >> 3) & 1) * 8;   // row within 16-row frag
    const int acol = lane >> 4;                             // 16B block parity (A)
    const int brow = (lane & 7) + ((lane >> 4) & 1) * 8;    // row within 16-row frag (B)
    const int bcol = (lane >> 3) & 1;

    for (int c = 0; c < nch; c++) {
        if (c + 1 < nch) issue_chunk(c + 1);
        if (c + 1 < nch) cp_wait<1>(); else cp_wait<0>();
        __syncthreads();

        const int st = c & 1;
        const uint32_t sAhi = abase + st * STAGE;
        const uint32_t sAlo = sAhi + A_TILE;
        const uint32_t sBhi = sAhi + 2 * A_TILE;
        const uint32_t sBlo = sBhi + B_TILE;

#pragma unroll
        for (int ks = 0; ks < 4; ks++) {
            uint32_t af[4][4], bf[4][4];
            // ---- pass 1: Alo x Bhi ----
#pragma unroll
            for (int mi = 0; mi < 4; mi++) {
                const int row = wm * 64 + mi * 16 + arow;
                const int cc  = ks * 2 + acol;
                ldsm4(af[mi], sAlo + (row << 7) + ((cc ^ (row & 7)) << 4));
            }
#pragma unroll
            for (int nj = 0; nj < 4; nj++) {
                const int row = wn * 64 + nj * 16 + brow;
                const int cc  = ks * 2 + bcol;
                ldsm4(bf[nj], sBhi + (row << 7) + ((cc ^ (row & 7)) << 4));
            }
#pragma unroll
            for (int mi = 0; mi < 4; mi++)
#pragma unroll
                for (int nj = 0; nj < 4; nj++) {
                    mma16816(acc[mi][2 * nj],     af[mi], &bf[nj][0]);
                    mma16816(acc[mi][2 * nj + 1], af[mi], &bf[nj][2]);
                }
            // ---- pass 2: Ahi x Bhi (swap A only) ----
#pragma unroll
            for (int mi = 0; mi < 4; mi++) {
                const int row = wm * 64 + mi * 16 + arow;
                const int cc  = ks * 2 + acol;
                ldsm4(af[mi], sAhi + (row << 7) + ((cc ^ (row & 7)) << 4));
            }
#pragma unroll
            for (int mi = 0; mi < 4; mi++)
#pragma unroll
                for (int nj = 0; nj < 4; nj++) {
                    mma16816(acc[mi][2 * nj],     af[mi], &bf[nj][0]);
                    mma16816(acc[mi][2 * nj + 1], af[mi], &bf[nj][2]);
                }
            // ---- pass 3: Ahi x Blo (swap B only) ----
#pragma unroll
            for (int nj = 0; nj < 4; nj++) {
                const int row = wn * 64 + nj * 16 + brow;
                const int cc  = ks * 2 + bcol;
                ldsm4(bf[nj], sBlo + (row << 7) + ((cc ^ (row & 7)) << 4));
            }
#pragma unroll
            for (int mi = 0; mi < 4; mi++)
#pragma unroll
                for (int nj = 0; nj < 4; nj++) {
                    mma16816(acc[mi][2 * nj],     af[mi], &bf[nj][0]);
                    mma16816(acc[mi][2 * nj + 1], af[mi], &bf[nj][2]);
                }
        }
        __syncthreads();
    }

    // ------------------------- epilogue (register accumulators) --------------
    const int gq = lane >> 2, tg = lane & 3;
#pragma unroll
    for (int mi = 0; mi < 4; mi++) {
#pragma unroll
        for (int half = 0; half < 2; half++) {
            const int gm = mBase + wm * 64 + mi * 16 + gq + half * 8;
#pragma unroll
            for (int ni = 0; ni < 8; ni++) {
                const int gn = nBase + wn * 64 + ni * 8 + 2 * tg;
                const float v0 = acc[mi][ni][half * 2 + 0];
                const float v1 = acc[mi][ni][half * 2 + 1];

                if (EPI == 0) {
                    float2 v;
                    v.x = v0 + g.bias[gn + 0];
                    v.y = v1 + g.bias[gn + 1];
                    *reinterpret_cast<float2*>(
                        g.outF + (long)bz * g.bsO + (long)gm * g.ldo + gn) = v;
                } else if (EPI == 1) {
                    float w0 = v0, w1 = v1;
                    if (g.bias) { w0 += g.bias[gn + 0]; w1 += g.bias[gn + 1]; }
                    const __nv_bfloat16 h0 = __float2bfloat16(w0);
                    const __nv_bfloat16 h1 = __float2bfloat16(w1);
                    const __nv_bfloat16 l0 = __float2bfloat16(w0 - __bfloat162float(h0));
                    const __nv_bfloat16 l1 = __float2bfloat16(w1 - __bfloat162float(h1));
                    __nv_bfloat16* o = g.outH + (long)bz * g.bsO + (long)gm * g.ldo + gn;
                    *reinterpret_cast<__nv_bfloat162*>(o) = __nv_bfloat162(h0, h1);
                    *reinterpret_cast<__nv_bfloat162*>(o + g.loOff) = __nv_bfloat162(l0, l1);
                } else {  // EPI == 3 : scores
                    float2 v;
                    v.x = (gn + 0 > gm) ? neg_inf_f() : v0 * g.scale;
                    v.y = (gn + 1 > gm) ? neg_inf_f() : v1 * g.scale;
                    *reinterpret_cast<float2*>(
                        g.outF + (long)bz * g.bsO + (long)gm * g.ldo + gn) = v;
                }
            }
        }
    }
}

// ---------------------------------------------------------------------------
// fp32 -> split bf16 [m][2*1024] (K fixed at 1024); 8B vector stores
// ---------------------------------------------------------------------------
__global__ void conv_split_k1024(const float* __restrict__ in,
                                 __nv_bfloat16* __restrict__ out, long n4)
{
    const long i = (long)blockIdx.x * 256 + threadIdx.x;
    if (i >= n4) return;
    const float4 v = reinterpret_cast<const float4*>(in)[i];
    const long idx = i * 4;
    const long m = idx >> 10;
    const int  k = (int)(idx & 1023);

    const __nv_bfloat16 h0 = __float2bfloat16(v.x);
    const __nv_bfloat16 h1 = __float2bfloat16(v.y);
    const __nv_bfloat16 h2 = __float2bfloat16(v.z);
    const __nv_bfloat16 h3 = __float2bfloat16(v.w);
    uint2 hp, lp;
    hp.x = pack_bf2(v.x, v.y);
    hp.y = pack_bf2(v.z, v.w);
    lp.x = pack_bf2(v.x - __bfloat162float(h0), v.y - __bfloat162float(h1));
    lp.y = pack_bf2(v.z - __bfloat162float(h2), v.w - __bfloat162float(h3));

    __nv_bfloat16* o = out + m * 2048 + k;
    *reinterpret_cast<uint2*>(o)        = hp;
    *reinterpret_cast<uint2*>(o + 1024) = lp;
}

// ---------------------------------------------------------------------------
// V fp32 [s*B+b][d] -> Vt split [b][d][hi(S)|lo(S)]
// ---------------------------------------------------------------------------
__global__ void transpose_split_v(const float* __restrict__ Vf,
                                  __nv_bfloat16* __restrict__ Vt)
{
    __shared__ float t[32][33];
    const int d0 = blockIdx.x * 32, s0 = blockIdx.y * 32, b = blockIdx.z;
    const int tx = threadIdx.x, ty = threadIdx.y;
#pragma unroll
    for (int r = 0; r < 32; r += 8)
        t[r + ty][tx] = Vf[((size_t)(s0 + r + ty) * B_ + b) * D_ + d0 + tx];
    __syncthreads();
#pragma unroll
    for (int r = 0; r < 32; r += 8) {
        const int d = d0 + r + ty, s = s0 + tx;
        const float v = t[tx][r + ty];
        const __nv_bfloat16 h = __float2bfloat16(v);
        __nv_bfloat16* o = Vt + ((size_t)b * D_ + d) * (2 * S_) + s;
        o[0]  = h;
        o[S_] = __float2bfloat16(v - __bfloat162float(h));
    }
}

// ---------------------------------------------------------------------------
// Fused row softmax + split-bf16 emit.
// ---------------------------------------------------------------------------
__global__ void __launch_bounds__(256) softmax_split(const float* __restrict__ P,
                                                     __nv_bfloat16* __restrict__ Pb)
{
    const int i = blockIdx.x, b = blockIdx.y;
    const float* p = P + ((size_t)b * S_ + i) * S_;
    __nv_bfloat16* o = Pb + ((size_t)b * S_ + i) * (2 * S_);
    const int jEnd = ((i >> 7) + 1) << 7;
    const int tid = threadIdx.x;
    __shared__ float sm[8];

    float m = neg_inf_f();
    for (int j = tid * 2; j < jEnd; j += 512) {
        const float2 v = *reinterpret_cast<const float2*>(p + j);
        m = fmaxf(m, fmaxf(v.x, v.y));
    }
#pragma unroll
    for (int off = 16; off > 0; off >>= 1) m = fmaxf(m, __shfl_xor_sync(0xffffffffu, m, off));
    if ((tid & 31) == 0) sm[tid >> 5] = m;
    __syncthreads();
    const float rowmax = fmaxf(fmaxf(fmaxf(sm[0], sm[1]), fmaxf(sm[2], sm[3])),
                               fmaxf(fmaxf(sm[4], sm[5]), fmaxf(sm[6], sm[7])));
    __syncthreads();

    float s = 0.0f;
    for (int j = tid * 2; j < jEnd; j += 512) {
        const float2 v = *reinterpret_cast<const float2*>(p + j);
        s += expf(v.x - rowmax) + expf(v.y - rowmax);
    }
#pragma unroll
    for (int off = 16; off > 0; off >>= 1) s += __shfl_xor_sync(0xffffffffu, s, off);
    if ((tid & 31) == 0) sm[tid >> 5] = s;
    __syncthreads();
    const float inv = 1.0f / ((sm[0] + sm[1]) + (sm[2] + sm[3]) + (sm[4] + sm[5]) + (sm[6] + sm[7]));

    for (int j = tid * 2; j < jEnd; j += 512) {
        const float2 v = *reinterpret_cast<const float2*>(p + j);
        const float e0 = expf(v.x - rowmax) * inv;
        const float e1 = expf(v.y - rowmax) * inv;
        const __nv_bfloat16 h0 = __float2bfloat16(e0);
        const __nv_bfloat16 h1 = __float2bfloat16(e1);
        *reinterpret_cast<uint32_t*>(o + j) = pack_bf2(e0, e1);
        *reinterpret_cast<uint32_t*>(o + S_ + j) =
            pack_bf2(e0 - __bfloat162float(h0), e1 - __bfloat162float(h1));
    }
}

// ---------------------------------------------------------------------------
extern "C" void kernel_launch(void* const* d_in, const int* in_sizes, int n_in,
                              void* d_out, int out_size)
{
    const float* query = (const float*)d_in[0];
    const float* key   = (const float*)d_in[1];
    const float* value = (const float*)d_in[2];
    const float* Wq = (const float*)d_in[4];
    const float* bq = (const float*)d_in[5];
    const float* Wk = (const float*)d_in[6];
    const float* bk = (const float*)d_in[7];
    const float* Wv = (const float*)d_in[8];
    const float* bv = (const float*)d_in[9];
    const float* Wo = (const float*)d_in[10];
    const float* bo = (const float*)d_in[11];
    float* out = (float*)d_out;

    __nv_bfloat16 *Abf, *Wbf, *Qbf, *Kbf, *Vt, *Pbf, *Xbf;
    float *Vf, *P;
    cudaGetSymbolAddress((void**)&Abf, g_Abf);
    cudaGetSymbolAddress((void**)&Wbf, g_Wbf);
    cudaGetSymbolAddress((void**)&Qbf, g_Qbf);
    cudaGetSymbolAddress((void**)&Kbf, g_Kbf);
    cudaGetSymbolAddress((void**)&Vf,  g_Vf);
    cudaGetSymbolAddress((void**)&Vt,  g_Vt);
    cudaGetSymbolAddress((void**)&P,   g_P);
    cudaGetSymbolAddress((void**)&Pbf, g_Pbf);
    cudaGetSymbolAddress((void**)&Xbf, g_Xbf);

    cudaFuncSetAttribute(gemm_split<0, false, false>,
                         cudaFuncAttributeMaxDynamicSharedMemorySize, GEMM_SMEM);
    cudaFuncSetAttribute(gemm_split<1, false, false>,
                         cudaFuncAttributeMaxDynamicSharedMemorySize, GEMM_SMEM);
    cudaFuncSetAttribute(gemm_split<1, true, false>,
                         cudaFuncAttributeMaxDynamicSharedMemorySize, GEMM_SMEM);
    cudaFuncSetAttribute(gemm_split<3, false, true>,
                         cudaFuncAttributeMaxDynamicSharedMemorySize, GEMM_SMEM);

    const long wlen = (long)D_ * 2 * D_;
    const long n4w  = (long)D_ * D_ / 4;
    const long n4i  = (long)M_ * D_ / 4;

    // Weight conversions
    conv_split_k1024<<<(unsigned)((n4w + 255) / 256), 256>>>(Wq, Wbf + 0 * wlen, n4w);
    conv_split_k1024<<<(unsigned)((n4w + 255) / 256), 256>>>(Wk, Wbf + 1 * wlen, n4w);
    conv_split_k1024<<<(unsigned)((n4w + 255) / 256), 256>>>(Wv, Wbf + 2 * wlen, n4w);
    conv_split_k1024<<<(unsigned)((n4w + 255) / 256), 256>>>(Wo, Wbf + 3 * wlen, n4w);

    GArgs a{};
    a.Kpart = D_;
    a.scale = 1.0f;

    const dim3 gproj(D_ / 128, M_ / 256, 1);

    // ---- Q projection ----
    conv_split_k1024<<<(unsigned)((n4i + 255) / 256), 256>>>(query, Abf, n4i);
    a.A = Abf; a.lda = 2 * D_; a.bsA = 0; a.oAlo = D_;
    a.B = Wbf + 0 * wlen; a.ldb = 2 * D_; a.bsB = 0; a.oBlo = D_;
    a.bias = bq; a.outH = Qbf; a.ldo = 2 * D_; a.bsO = 0; a.loOff = D_;
    gemm_split<1, false, false><<<gproj, 256, GEMM_SMEM>>>(a);

    // ---- K projection ----
    conv_split_k1024<<<(unsigned)((n4i + 255) / 256), 256>>>(key, Abf, n4i);
    a.B = Wbf + 1 * wlen; a.bias = bk; a.outH = Kbf;
    gemm_split<1, false, false><<<gproj, 256, GEMM_SMEM>>>(a);

    // ---- V projection (fp32 out) + transpose/split ----
    conv_split_k1024<<<(unsigned)((n4i + 255) / 256), 256>>>(value, Abf, n4i);
    a.B = Wbf + 2 * wlen; a.bias = bv; a.outH = nullptr;
    a.outF = Vf; a.ldo = D_; a.bsO = 0;
    gemm_split<0, false, false><<<gproj, 256, GEMM_SMEM>>>(a);
    transpose_split_v<<<dim3(D_ / 32, S_ / 32, B_), dim3(32, 8)>>>(Vf, Vt);

    // ---- Scores: P[b][i][j] = SCALE * <q_i, k_j>, tril tiles, causal mask ----
    GArgs sc{};
    sc.A = Qbf; sc.lda = (long)B_ * 2 * D_; sc.bsA = 2 * D_; sc.oAlo = D_;
    sc.B = Kbf; sc.ldb = (long)B_ * 2 * D_; sc.bsB = 2 * D_; sc.oBlo = D_;
    sc.Kpart = D_; sc.scale = SCALE_; sc.bias = nullptr;
    sc.outF = P; sc.ldo = S_; sc.bsO = (long)S_ * S_;
    gemm_split<3, false, true><<<dim3(S_ / 128, S_ / 256, B_), 256, GEMM_SMEM>>>(sc);

    // ---- fused softmax + P split ----
    softmax_split<<<dim3(S_, B_), 256>>>(P, Pbf);

    // ---- X = P @ V (causal K bound), split-bf16 out ----
    GArgs pv{};
    pv.A = Pbf; pv.lda = 2 * S_; pv.bsA = (long)S_ * 2 * S_; pv.oAlo = S_;
    pv.B = Vt; pv.ldb = 2 * S_; pv.bsB = (long)D_ * 2 * S_; pv.oBlo = S_;
    pv.Kpart = S_; pv.scale = 1.0f; pv.bias = nullptr;
    pv.outH = Xbf; pv.ldo = (long)B_ * 2 * D_; pv.bsO = 2 * D_; pv.loOff = D_;
    gemm_split<1, true, false><<<dim3(D_ / 128, S_ / 256, B_), 256, GEMM_SMEM>>>(pv);

    // ---- Output projection (fp32 to d_out) ----
    GArgs op{};
    op.A = Xbf; op.lda = 2 * D_; op.bsA = 0; op.oAlo = D_;
    op.B = Wbf + 3 * wlen; op.ldb = 2 * D_; op.bsB = 0; op.oBlo = D_;
    op.Kpart = D_; op.scale = 1.0f; op.bias = bo;
    op.outF = out; op.ldo = D_; op.bsO = 0;
    gemm_split<0, false, false><<<gproj, 256, GEMM_SMEM>>>(op);
}